// round 1
// baseline (speedup 1.0000x reference)
#include <cuda_runtime.h>
#include <cstdint>

#define NSEG 4096
#define DIM  128
#define NGRP 1024            // NSEG/4
#define C_EXP2  14.426950408889634f   // (1/T)/ln2 = 10/ln2
#define EXP10   22026.465794806718f   // exp(1/T) = exp(10)

// ---------------- device scratch (static: no allocations allowed) ----------
__device__ float g_FnT[DIM * NSEG];          // normalized feats, TRANSPOSED [k][n], 2 MB
__device__ float g_E[16777216];              // exp(S/T), row-major [4096][4096], 64 MB
__device__ float g_RSpart[32 * NSEG];        // per-colblock row-sum partials
__device__ float g_RS[NSEG];                 // full row sums of E
__device__ float g_rowL[NSEG];               // per-row log-sum partial
__device__ float g_rowP[NSEG];               // per-row pair (S/T) partial

// ---------------- kernel 1: normalize rows + transpose into g_FnT ----------
__global__ void k_norm_t(const float* __restrict__ feats) {
    __shared__ float s[64 * 129];
    __shared__ float sinv[64];
    const int rowbase = blockIdx.x * 64;
    const int tid = threadIdx.x;

    // coalesced load of 64x128 tile into padded smem
    for (int idx = tid; idx < 64 * 32; idx += 256) {
        int r = idx >> 5, c4 = idx & 31;
        float4 v = *reinterpret_cast<const float4*>(&feats[(rowbase + r) * DIM + c4 * 4]);
        float* p = &s[r * 129 + c4 * 4];
        p[0] = v.x; p[1] = v.y; p[2] = v.z; p[3] = v.w;
    }
    __syncthreads();

    if (tid < 64) {
        float sum = 0.f;
        #pragma unroll 8
        for (int c = 0; c < 128; ++c) { float v = s[tid * 129 + c]; sum = fmaf(v, v, sum); }
        float inv = rsqrtf(sum);
        inv = inv * (1.5f - 0.5f * sum * inv * inv);   // NR refine
        sinv[tid] = inv;
    }
    __syncthreads();

    // transposed, coalesced store: g_FnT[k][rowbase + r]
    for (int idx = tid; idx < 64 * 128; idx += 256) {
        int k = idx >> 6, r = idx & 63;
        g_FnT[k * NSEG + rowbase + r] = s[r * 129 + k] * sinv[r];
    }
}

// ---------------- kernel 2: 128x128-tile fp32 GEMM -> exp -> store E -------
#define PADB 132
#define SMEM2 (2 * 128 * PADB * 4)

__global__ void k_gemm_exp() {
    extern __shared__ float smem[];
    float* As = smem;                 // [k][m], k rows of PADB
    float* Bs = smem + 128 * PADB;    // [k][n]
    const int rowbase = blockIdx.y * 128;
    const int colbase = blockIdx.x * 128;
    const int tid = threadIdx.x;

    // both tiles come straight out of the transposed g_FnT: coalesced, no scatter
    for (int idx = tid; idx < 128 * 32; idx += 256) {
        int k = idx >> 5, c4 = (idx & 31) * 4;
        float4 a = *reinterpret_cast<const float4*>(&g_FnT[k * NSEG + rowbase + c4]);
        float4 b = *reinterpret_cast<const float4*>(&g_FnT[k * NSEG + colbase + c4]);
        *reinterpret_cast<float4*>(&As[k * PADB + c4]) = a;
        *reinterpret_cast<float4*>(&Bs[k * PADB + c4]) = b;
    }
    __syncthreads();

    const int tx = tid & 15, ty = tid >> 4;
    const int am = ty * 8, bn = tx * 8;
    float acc[8][8];
    #pragma unroll
    for (int i = 0; i < 8; ++i)
        #pragma unroll
        for (int j = 0; j < 8; ++j) acc[i][j] = 0.f;

    #pragma unroll 4
    for (int k = 0; k < 128; ++k) {
        float4 a0 = *reinterpret_cast<float4*>(&As[k * PADB + am]);
        float4 a1 = *reinterpret_cast<float4*>(&As[k * PADB + am + 4]);
        float4 b0 = *reinterpret_cast<float4*>(&Bs[k * PADB + bn]);
        float4 b1 = *reinterpret_cast<float4*>(&Bs[k * PADB + bn + 4]);
        float a[8] = {a0.x, a0.y, a0.z, a0.w, a1.x, a1.y, a1.z, a1.w};
        float b[8] = {b0.x, b0.y, b0.z, b0.w, b1.x, b1.y, b1.z, b1.w};
        #pragma unroll
        for (int i = 0; i < 8; ++i)
            #pragma unroll
            for (int j = 0; j < 8; ++j)
                acc[i][j] = fmaf(a[i], b[j], acc[i][j]);
    }

    // epilogue: exp(S/T) via exp2, row-sum partials, store E
    float rsum[8];
    #pragma unroll
    for (int i = 0; i < 8; ++i) {
        float e[8];
        float rs = 0.f;
        #pragma unroll
        for (int j = 0; j < 8; ++j) { e[j] = exp2f(acc[i][j] * C_EXP2); rs += e[j]; }
        rsum[i] = rs;
        size_t base = (size_t)(rowbase + am + i) * NSEG + colbase + bn;
        float4 v0 = {e[0], e[1], e[2], e[3]};
        float4 v1 = {e[4], e[5], e[6], e[7]};
        *reinterpret_cast<float4*>(&g_E[base])     = v0;
        *reinterpret_cast<float4*>(&g_E[base + 4]) = v1;
    }
    // reduce row partials across the 16 tx lanes (xor <= 8 stays in half-warp)
    #pragma unroll
    for (int i = 0; i < 8; ++i) {
        float v = rsum[i];
        #pragma unroll
        for (int off = 8; off > 0; off >>= 1) v += __shfl_xor_sync(0xffffffffu, v, off);
        rsum[i] = v;
    }
    if (tx == 0) {
        #pragma unroll
        for (int i = 0; i < 8; ++i)
            g_RSpart[blockIdx.x * NSEG + rowbase + am + i] = rsum[i];
    }
}

// ---------------- kernel 2.5: deterministic row-sum combine ----------------
__global__ void k_rssum() {
    int r = blockIdx.x * blockDim.x + threadIdx.x;
    float s = 0.f;
    #pragma unroll
    for (int j = 0; j < 32; ++j) s += g_RSpart[j * NSEG + r];
    g_RS[r] = s;
}

// ---------------- kernel 3: per-row loss reduction -------------------------
__global__ void k_loss() {
    const int r = blockIdx.x;
    const int t = threadIdx.x;
    const float rs = g_RS[r];
    const int gr = r >> 2;
    const int kk = r & 3;
    const float4* Er = reinterpret_cast<const float4*>(&g_E[(size_t)r * NSEG]);

    float acc = 0.f, accp = 0.f;
    #pragma unroll
    for (int it = 0; it < 4; ++it) {
        int g = t + it * 256;
        float4 e = Er[g];
        float gs = (e.x + e.y) + (e.z + e.w);
        float base = rs - gs - EXP10;
        if (g != gr) {
            acc += __logf(base + e.x + e.y) + __logf(base + e.x + e.z)
                 + __logf(base + e.x + e.w) + __logf(base + e.y + e.z)
                 + __logf(base + e.y + e.w) + __logf(base + e.z + e.w);
        } else {
            // own group: only pairs containing local index kk count (rows i or j);
            // also collect the ordered-pair -S[i,j]/T = -ln(E[r,j]) terms.
            float ee[4] = {e.x, e.y, e.z, e.w};
            #pragma unroll
            for (int a = 0; a < 4; ++a)
                #pragma unroll
                for (int b = a + 1; b < 4; ++b)
                    if (a == kk || b == kk) acc += __logf(base + ee[a] + ee[b]);
            #pragma unroll
            for (int m = 0; m < 4; ++m)
                if (m != kk) accp += __logf(ee[m]);
        }
    }

    // block reduce (deterministic tree)
    #pragma unroll
    for (int off = 16; off > 0; off >>= 1) {
        acc  += __shfl_down_sync(0xffffffffu, acc,  off);
        accp += __shfl_down_sync(0xffffffffu, accp, off);
    }
    __shared__ float wa[8], wp[8];
    if ((t & 31) == 0) { wa[t >> 5] = acc; wp[t >> 5] = accp; }
    __syncthreads();
    if (t == 0) {
        float a = 0.f, p = 0.f;
        #pragma unroll
        for (int w = 0; w < 8; ++w) { a += wa[w]; p += wp[w]; }
        g_rowL[r] = a;
        g_rowP[r] = p;
    }
}

// ---------------- kernel 4: final deterministic combine --------------------
__global__ void k_finalize(float* __restrict__ out) {
    __shared__ double sa[256], sp[256];
    int t = threadIdx.x;
    double a = 0.0, p = 0.0;
    for (int r = t; r < NSEG; r += 256) { a += (double)g_rowL[r]; p += (double)g_rowP[r]; }
    sa[t] = a; sp[t] = p;
    __syncthreads();
    for (int s = 128; s > 0; s >>= 1) {
        if (t < s) { sa[t] += sa[t + s]; sp[t] += sp[t + s]; }
        __syncthreads();
    }
    if (t == 0) out[0] = (float)(sa[0] * (2.0 / 4094.0) - sp[0]);
}

// ---------------- launch ---------------------------------------------------
extern "C" void kernel_launch(void* const* d_in, const int* in_sizes, int n_in,
                              void* d_out, int out_size) {
    const float* feats = (const float*)d_in[0];
    float* out = (float*)d_out;

    cudaFuncSetAttribute(k_gemm_exp, cudaFuncAttributeMaxDynamicSharedMemorySize, SMEM2);

    k_norm_t<<<64, 256>>>(feats);
    k_gemm_exp<<<dim3(32, 32), 256, SMEM2>>>();
    k_rssum<<<16, 256>>>();
    k_loss<<<NSEG, 256>>>();
    k_finalize<<<1, 256>>>(out);
}

// round 3
// speedup vs baseline: 1.7816x; 1.7816x over previous
#include <cuda_runtime.h>
#include <cstdint>

#define NSEG 4096
#define DIM  128
#define C_EXP2  14.426950408889634f   // (1/T)/ln2 = 10/ln2
#define EXP10   22026.465794806718f   // exp(1/T) = exp(10)

// ---------------- device scratch (static: no allocations allowed) ----------
__device__ float g_Fn[NSEG * DIM];           // normalized feats [m][k], tf32-rounded, 2 MB
__device__ float g_E[16777216];              // exp(S/T), row-major [4096][4096], 64 MB
__device__ float g_RSpart[64 * NSEG];        // per-(colblock,warpcol) row-sum partials
__device__ float g_RS[NSEG];                 // full row sums of E
__device__ float g_rowL[NSEG];               // per-row log-sum partial
__device__ float g_rowP[NSEG];               // per-row pair (S/T) partial

// ---------------- kernel 1: normalize rows -> g_Fn (tf32-rounded) ----------
__global__ void k_norm(const float* __restrict__ feats) {
    __shared__ float s[64 * 129];
    __shared__ float sinv[64];
    const int rowbase = blockIdx.x * 64;
    const int tid = threadIdx.x;

    for (int idx = tid; idx < 64 * 32; idx += 256) {
        int r = idx >> 5, c4 = idx & 31;
        float4 v = *reinterpret_cast<const float4*>(&feats[(rowbase + r) * DIM + c4 * 4]);
        float* p = &s[r * 129 + c4 * 4];
        p[0] = v.x; p[1] = v.y; p[2] = v.z; p[3] = v.w;
    }
    __syncthreads();

    if (tid < 64) {
        float sum = 0.f;
        #pragma unroll 8
        for (int c = 0; c < 128; ++c) { float v = s[tid * 129 + c]; sum = fmaf(v, v, sum); }
        float inv = rsqrtf(sum);
        inv = inv * (1.5f - 0.5f * sum * inv * inv);   // NR refine
        sinv[tid] = inv;
    }
    __syncthreads();

    for (int idx = tid; idx < 64 * 128; idx += 256) {
        int r = idx >> 7, k = idx & 127;
        float v = s[r * 129 + k] * sinv[r];
        uint32_t u;
        asm("cvt.rna.tf32.f32 %0, %1;" : "=r"(u) : "f"(v));  // pre-round so HMMA truncation == rna
        g_Fn[(rowbase + r) * DIM + k] = __uint_as_float(u);
    }
}

// ---------------- kernel 2: HMMA tf32 GEMM -> exp -> store E ---------------
// CTA tile 128x128, 8 warps as 4 (rows) x 2 (cols); warp tile 32x64.
// mma.sync.m16n8k8 tf32: warp does 2 m-tiles x 8 n-tiles per k-step, 16 k-steps.
#define LDP 132                       // padded row stride (132 % 32 == 4 -> conflict-free frags)
#define SMEM2 (2 * 128 * LDP * 4)     // 135168 B

__global__ void __launch_bounds__(256, 1) k_gemm_exp() {
    extern __shared__ float smem[];
    float* As = smem;                 // [m][k], rows rowbase+m
    float* Bs = smem + 128 * LDP;     // [n][k], rows colbase+n
    const int tid = threadIdx.x;
    const int w = tid >> 5, lane = tid & 31;
    const int g = lane >> 2, t = lane & 3;          // quad group / thread-in-group
    const int warp_m = w & 3, warp_n = w >> 2;      // 4x2 warp grid
    const int rowbase = blockIdx.y * 128;
    const int colbase = blockIdx.x * 128;

    // coalesced tile fill (g_Fn is tf32-exact already)
    for (int idx = tid; idx < 128 * 32; idx += 256) {
        int m = idx >> 5, c4 = (idx & 31) * 4;
        float4 a = *reinterpret_cast<const float4*>(&g_Fn[(rowbase + m) * DIM + c4]);
        float4 b = *reinterpret_cast<const float4*>(&g_Fn[(colbase + m) * DIM + c4]);
        *reinterpret_cast<float4*>(&As[m * LDP + c4]) = a;
        *reinterpret_cast<float4*>(&Bs[m * LDP + c4]) = b;
    }
    __syncthreads();

    float c[2][8][4];
    #pragma unroll
    for (int mt = 0; mt < 2; ++mt)
        #pragma unroll
        for (int nt = 0; nt < 8; ++nt)
            #pragma unroll
            for (int q = 0; q < 4; ++q) c[mt][nt][q] = 0.f;

    const float* Arow = &As[(warp_m * 32 + g) * LDP + t];      // row g (row g+8 at +8*LDP)
    const float* Brow = &Bs[(warp_n * 64 + g) * LDP + t];

    #pragma unroll
    for (int ks = 0; ks < 16; ++ks) {
        const int k0 = ks * 8;
        uint32_t a[2][4], b[8][2];
        #pragma unroll
        for (int mt = 0; mt < 2; ++mt) {
            const float* p = Arow + mt * 16 * LDP + k0;
            a[mt][0] = __float_as_uint(p[0]);
            a[mt][1] = __float_as_uint(p[8 * LDP]);
            a[mt][2] = __float_as_uint(p[4]);
            a[mt][3] = __float_as_uint(p[8 * LDP + 4]);
        }
        #pragma unroll
        for (int nt = 0; nt < 8; ++nt) {
            const float* p = Brow + nt * 8 * LDP + k0;
            b[nt][0] = __float_as_uint(p[0]);
            b[nt][1] = __float_as_uint(p[4]);
        }
        #pragma unroll
        for (int mt = 0; mt < 2; ++mt)
            #pragma unroll
            for (int nt = 0; nt < 8; ++nt)
                asm volatile(
                    "mma.sync.aligned.m16n8k8.row.col.f32.tf32.tf32.f32 "
                    "{%0,%1,%2,%3}, {%4,%5,%6,%7}, {%8,%9}, {%0,%1,%2,%3};"
                    : "+f"(c[mt][nt][0]), "+f"(c[mt][nt][1]),
                      "+f"(c[mt][nt][2]), "+f"(c[mt][nt][3])
                    : "r"(a[mt][0]), "r"(a[mt][1]), "r"(a[mt][2]), "r"(a[mt][3]),
                      "r"(b[nt][0]), "r"(b[nt][1]));
    }

    // epilogue: exp(S/T), row-sum partials, store E
    // C frag: c0:(row g, col 2t) c1:(g, 2t+1) c2:(g+8, 2t) c3:(g+8, 2t+1)
    float rs0[2] = {0.f, 0.f}, rs1[2] = {0.f, 0.f};
    #pragma unroll
    for (int mt = 0; mt < 2; ++mt) {
        const int r_lo = rowbase + warp_m * 32 + mt * 16 + g;
        #pragma unroll
        for (int nt = 0; nt < 8; ++nt) {
            const int col = colbase + warp_n * 64 + nt * 8 + 2 * t;
            float e0 = exp2f(c[mt][nt][0] * C_EXP2);
            float e1 = exp2f(c[mt][nt][1] * C_EXP2);
            float e2 = exp2f(c[mt][nt][2] * C_EXP2);
            float e3 = exp2f(c[mt][nt][3] * C_EXP2);
            rs0[mt] += e0 + e1;
            rs1[mt] += e2 + e3;
            *reinterpret_cast<float2*>(&g_E[(size_t)r_lo * NSEG + col])       = make_float2(e0, e1);
            *reinterpret_cast<float2*>(&g_E[(size_t)(r_lo + 8) * NSEG + col]) = make_float2(e2, e3);
        }
    }
    // reduce over the 4 lanes of each quad (same row)
    #pragma unroll
    for (int mt = 0; mt < 2; ++mt) {
        #pragma unroll
        for (int off = 1; off <= 2; off <<= 1) {
            rs0[mt] += __shfl_xor_sync(0xffffffffu, rs0[mt], off);
            rs1[mt] += __shfl_xor_sync(0xffffffffu, rs1[mt], off);
        }
    }
    if (t == 0) {
        const int part = blockIdx.x * 2 + warp_n;
        const int r0 = rowbase + warp_m * 32;
        #pragma unroll
        for (int mt = 0; mt < 2; ++mt) {
            g_RSpart[part * NSEG + r0 + mt * 16 + g]     = rs0[mt];
            g_RSpart[part * NSEG + r0 + mt * 16 + g + 8] = rs1[mt];
        }
    }
}

// ---------------- kernel 2.5: deterministic row-sum combine ----------------
__global__ void k_rssum() {
    int r = blockIdx.x * blockDim.x + threadIdx.x;
    float s = 0.f;
    #pragma unroll
    for (int j = 0; j < 64; ++j) s += g_RSpart[j * NSEG + r];
    g_RS[r] = s;
}

// ---------------- kernel 3: per-row loss reduction -------------------------
__global__ void k_loss() {
    const int r = blockIdx.x;
    const int t = threadIdx.x;
    const float rs = g_RS[r];
    const int gr = r >> 2;
    const int kk = r & 3;
    const float4* Er = reinterpret_cast<const float4*>(&g_E[(size_t)r * NSEG]);

    // front-batch the 4 loads (MLP=4) before any dependent math
    float4 e4[4];
    #pragma unroll
    for (int it = 0; it < 4; ++it) e4[it] = Er[t + it * 256];

    float acc = 0.f, accp = 0.f;
    #pragma unroll
    for (int it = 0; it < 4; ++it) {
        int gcol = t + it * 256;
        float4 e = e4[it];
        float gs = (e.x + e.y) + (e.z + e.w);
        float base = rs - gs - EXP10;
        if (gcol != gr) {
            acc += __logf(base + e.x + e.y) + __logf(base + e.x + e.z)
                 + __logf(base + e.x + e.w) + __logf(base + e.y + e.z)
                 + __logf(base + e.y + e.w) + __logf(base + e.z + e.w);
        } else {
            float ee[4] = {e.x, e.y, e.z, e.w};
            #pragma unroll
            for (int a = 0; a < 4; ++a)
                #pragma unroll
                for (int b = a + 1; b < 4; ++b)
                    if (a == kk || b == kk) acc += __logf(base + ee[a] + ee[b]);
            #pragma unroll
            for (int m = 0; m < 4; ++m)
                if (m != kk) accp += __logf(ee[m]);
        }
    }

    #pragma unroll
    for (int off = 16; off > 0; off >>= 1) {
        acc  += __shfl_down_sync(0xffffffffu, acc,  off);
        accp += __shfl_down_sync(0xffffffffu, accp, off);
    }
    __shared__ float wa[8], wp[8];
    if ((t & 31) == 0) { wa[t >> 5] = acc; wp[t >> 5] = accp; }
    __syncthreads();
    if (t == 0) {
        float a = 0.f, p = 0.f;
        #pragma unroll
        for (int ww = 0; ww < 8; ++ww) { a += wa[ww]; p += wp[ww]; }
        g_rowL[r] = a;
        g_rowP[r] = p;
    }
}

// ---------------- kernel 4: final deterministic combine --------------------
__global__ void k_finalize(float* __restrict__ out) {
    __shared__ double sa[256], sp[256];
    int t = threadIdx.x;
    double a = 0.0, p = 0.0;
    for (int r = t; r < NSEG; r += 256) { a += (double)g_rowL[r]; p += (double)g_rowP[r]; }
    sa[t] = a; sp[t] = p;
    __syncthreads();
    for (int s = 128; s > 0; s >>= 1) {
        if (t < s) { sa[t] += sa[t + s]; sp[t] += sp[t + s]; }
        __syncthreads();
    }
    if (t == 0) out[0] = (float)(sa[0] * (2.0 / 4094.0) - sp[0]);
}

// ---------------- launch ---------------------------------------------------
extern "C" void kernel_launch(void* const* d_in, const int* in_sizes, int n_in,
                              void* d_out, int out_size) {
    const float* feats = (const float*)d_in[0];
    float* out = (float*)d_out;

    cudaFuncSetAttribute(k_gemm_exp, cudaFuncAttributeMaxDynamicSharedMemorySize, SMEM2);

    k_norm<<<64, 256>>>(feats);
    k_gemm_exp<<<dim3(32, 32), 256, SMEM2>>>();
    k_rssum<<<16, 256>>>();
    k_loss<<<NSEG, 256>>>();
    k_finalize<<<1, 256>>>(out);
}

// round 4
// speedup vs baseline: 2.6113x; 1.4657x over previous
#include <cuda_runtime.h>
#include <cuda_fp16.h>
#include <cstdint>

#define NSEG 4096
#define DIM  128
#define C_EXP2  14.426950408889634f   // (1/T)/ln2 = 10/ln2
#define EXP10   22026.465794806718f   // exp(1/T) = exp(10)

// ---------------- device scratch (static: no allocations allowed) ----------
__device__ __half g_Fh[NSEG * DIM];          // normalized feats [m][k], fp16, 1 MB
__device__ float g_E[16777216];              // exp(S/T), row-major [4096][4096], 64 MB
__device__ float g_RSpart[32 * NSEG];        // per-colblock row-sum partials
__device__ float g_RS[NSEG];                 // full row sums of E
__device__ float g_rowL[NSEG];               // per-row log-sum partial
__device__ float g_rowP[NSEG];               // per-row pair (S/T) partial

// ---------------- kernel 1: normalize rows -> g_Fh (fp16), warp/row -------
__global__ void k_norm(const float* __restrict__ feats) {
    const int w = threadIdx.x >> 5, lane = threadIdx.x & 31;
    const int row = blockIdx.x * 8 + w;
    float4 v = *reinterpret_cast<const float4*>(&feats[row * DIM + lane * 4]);
    float sum = fmaf(v.x, v.x, fmaf(v.y, v.y, fmaf(v.z, v.z, v.w * v.w)));
    #pragma unroll
    for (int off = 16; off > 0; off >>= 1) sum += __shfl_xor_sync(0xffffffffu, sum, off);
    float inv = rsqrtf(sum);
    inv = inv * (1.5f - 0.5f * sum * inv * inv);   // NR refine
    __half2 h0 = __floats2half2_rn(v.x * inv, v.y * inv);
    __half2 h1 = __floats2half2_rn(v.z * inv, v.w * inv);
    *reinterpret_cast<__half2*>(&g_Fh[row * DIM + lane * 4])     = h0;
    *reinterpret_cast<__half2*>(&g_Fh[row * DIM + lane * 4 + 2]) = h1;
}

// ---------------- kernel 2: fp16 HMMA GEMM (upper-tri) -> exp -> E ---------
// Only tiles bi <= bj computed; off-diagonal tiles also store the transpose.
// CTA tile 128x128, 8 warps as 4(m) x 2(n); warp tile 32x64.
// mma.sync.m16n8k16 f16: warp does 2 m-tiles x 8 n-tiles per k-step, 8 k-steps.
#define LDH 136                       // padded row stride in halfs (conflict-free frags)
#define AB_BYTES (2 * 128 * LDH * 2)  // 69632
#define STG_STRIDE 129                // staging stride (floats) for transpose pass
#define RS_OFF  66048                 // bytes: rowsum halves [2][128]
#define CS_OFF  67072                 // bytes: colsum halves [128][2]
#define SMEM2   69632

__global__ void __launch_bounds__(256, 2) k_gemm_exp() {
    const int bi = blockIdx.y, bj = blockIdx.x;
    if (bi > bj) return;

    extern __shared__ char smem[];
    __half* As = reinterpret_cast<__half*>(smem);
    __half* Bs = As + 128 * LDH;
    const int tid = threadIdx.x;
    const int w = tid >> 5, lane = tid & 31;
    const int g = lane >> 2, t = lane & 3;          // quad group / thread-in-group
    const int warp_m = w & 3, warp_n = w >> 2;      // 4x2 warp grid
    const int rowbase = bi * 128;
    const int colbase = bj * 128;

    // coalesced tile fill (uint4 = 8 halfs)
    for (int idx = tid; idx < 128 * 16; idx += 256) {
        int m = idx >> 4, c8 = (idx & 15) * 8;
        uint4 a = *reinterpret_cast<const uint4*>(&g_Fh[(rowbase + m) * DIM + c8]);
        uint4 b = *reinterpret_cast<const uint4*>(&g_Fh[(colbase + m) * DIM + c8]);
        *reinterpret_cast<uint4*>(&As[m * LDH + c8]) = a;
        *reinterpret_cast<uint4*>(&Bs[m * LDH + c8]) = b;
    }
    __syncthreads();

    float c[2][8][4];
    #pragma unroll
    for (int mt = 0; mt < 2; ++mt)
        #pragma unroll
        for (int nt = 0; nt < 8; ++nt)
            #pragma unroll
            for (int q = 0; q < 4; ++q) c[mt][nt][q] = 0.f;

    const __half* Ar = &As[(warp_m * 32 + g) * LDH + 2 * t];
    const __half* Br = &Bs[(warp_n * 64 + g) * LDH + 2 * t];

    #pragma unroll
    for (int ks = 0; ks < 8; ++ks) {
        const int k0 = ks * 16;
        uint32_t a[2][4], b[8][2];
        #pragma unroll
        for (int mt = 0; mt < 2; ++mt) {
            const __half* p = Ar + mt * 16 * LDH + k0;
            a[mt][0] = *reinterpret_cast<const uint32_t*>(p);
            a[mt][1] = *reinterpret_cast<const uint32_t*>(p + 8 * LDH);
            a[mt][2] = *reinterpret_cast<const uint32_t*>(p + 8);
            a[mt][3] = *reinterpret_cast<const uint32_t*>(p + 8 * LDH + 8);
        }
        #pragma unroll
        for (int nt = 0; nt < 8; ++nt) {
            const __half* p = Br + nt * 8 * LDH + k0;
            b[nt][0] = *reinterpret_cast<const uint32_t*>(p);
            b[nt][1] = *reinterpret_cast<const uint32_t*>(p + 8);
        }
        #pragma unroll
        for (int mt = 0; mt < 2; ++mt)
            #pragma unroll
            for (int nt = 0; nt < 8; ++nt)
                asm volatile(
                    "mma.sync.aligned.m16n8k16.row.col.f32.f16.f16.f32 "
                    "{%0,%1,%2,%3}, {%4,%5,%6,%7}, {%8,%9}, {%0,%1,%2,%3};"
                    : "+f"(c[mt][nt][0]), "+f"(c[mt][nt][1]),
                      "+f"(c[mt][nt][2]), "+f"(c[mt][nt][3])
                    : "r"(a[mt][0]), "r"(a[mt][1]), "r"(a[mt][2]), "r"(a[mt][3]),
                      "r"(b[nt][0]), "r"(b[nt][1]));
    }

    __syncthreads();   // mainloop smem dead; reuse for staging

    float* stage = reinterpret_cast<float*>(smem);              // [128][129]
    float* rs    = reinterpret_cast<float*>(smem + RS_OFF);     // [2][128]
    float* cs    = reinterpret_cast<float*>(smem + CS_OFF);     // [128][2]
    const bool diag = (bi == bj);

    // pass 1: exp, direct store, stage (off-diag), row-sum partials
    // C frag: c0:(row g, col 2t) c1:(g,2t+1) c2:(g+8,2t) c3:(g+8,2t+1)
    float rs0[2] = {0.f, 0.f}, rs1[2] = {0.f, 0.f};
    #pragma unroll
    for (int mt = 0; mt < 2; ++mt) {
        const int rloc = warp_m * 32 + mt * 16 + g;
        #pragma unroll
        for (int nt = 0; nt < 8; ++nt) {
            const int cloc = warp_n * 64 + nt * 8 + 2 * t;
            float e0 = exp2f(c[mt][nt][0] * C_EXP2);
            float e1 = exp2f(c[mt][nt][1] * C_EXP2);
            float e2 = exp2f(c[mt][nt][2] * C_EXP2);
            float e3 = exp2f(c[mt][nt][3] * C_EXP2);
            rs0[mt] += e0 + e1;
            rs1[mt] += e2 + e3;
            *reinterpret_cast<float2*>(&g_E[(size_t)(rowbase + rloc) * NSEG + colbase + cloc])     = make_float2(e0, e1);
            *reinterpret_cast<float2*>(&g_E[(size_t)(rowbase + rloc + 8) * NSEG + colbase + cloc]) = make_float2(e2, e3);
            if (!diag) {
                stage[rloc * STG_STRIDE + cloc]           = e0;
                stage[rloc * STG_STRIDE + cloc + 1]       = e1;
                stage[(rloc + 8) * STG_STRIDE + cloc]     = e2;
                stage[(rloc + 8) * STG_STRIDE + cloc + 1] = e3;
            }
        }
    }
    #pragma unroll
    for (int mt = 0; mt < 2; ++mt) {
        #pragma unroll
        for (int off = 1; off <= 2; off <<= 1) {
            rs0[mt] += __shfl_xor_sync(0xffffffffu, rs0[mt], off);
            rs1[mt] += __shfl_xor_sync(0xffffffffu, rs1[mt], off);
        }
    }
    if (t == 0) {
        const int r0 = warp_m * 32;
        #pragma unroll
        for (int mt = 0; mt < 2; ++mt) {
            rs[warp_n * 128 + r0 + mt * 16 + g]     = rs0[mt];
            rs[warp_n * 128 + r0 + mt * 16 + g + 8] = rs1[mt];
        }
    }
    __syncthreads();
    if (tid < 128)
        g_RSpart[(size_t)bj * NSEG + rowbase + tid] = rs[tid] + rs[128 + tid];

    if (diag) return;

    // pass 2: transposed store E[bj rows, bi cols] + column sums
    {
        const int cc = tid >> 1;                 // output row (= column of tile)
        const int r0 = (tid & 1) * 64;
        float csum = 0.f;
        float* dst = &g_E[(size_t)(colbase + cc) * NSEG + rowbase + r0];
        #pragma unroll 4
        for (int j = 0; j < 64; j += 4) {
            float4 v = { stage[(r0 + j)     * STG_STRIDE + cc],
                         stage[(r0 + j + 1) * STG_STRIDE + cc],
                         stage[(r0 + j + 2) * STG_STRIDE + cc],
                         stage[(r0 + j + 3) * STG_STRIDE + cc] };
            csum += (v.x + v.y) + (v.z + v.w);
            *reinterpret_cast<float4*>(&dst[j]) = v;
        }
        cs[cc * 2 + (tid & 1)] = csum;
    }
    __syncthreads();
    if (tid < 128)
        g_RSpart[(size_t)bi * NSEG + colbase + tid] = cs[tid * 2] + cs[tid * 2 + 1];
}

// ---------------- kernel 2.5: deterministic row-sum combine ----------------
__global__ void k_rssum() {
    int r = blockIdx.x * blockDim.x + threadIdx.x;
    float s = 0.f;
    #pragma unroll
    for (int j = 0; j < 32; ++j) s += g_RSpart[j * NSEG + r];
    g_RS[r] = s;
}

// ---------------- kernel 3: per-row loss reduction -------------------------
__global__ void k_loss() {
    const int r = blockIdx.x;
    const int t = threadIdx.x;
    const float rs = g_RS[r];
    const int gr = r >> 2;
    const int kk = r & 3;
    const float4* Er = reinterpret_cast<const float4*>(&g_E[(size_t)r * NSEG]);

    float4 e4[4];
    #pragma unroll
    for (int it = 0; it < 4; ++it) e4[it] = Er[t + it * 256];

    float acc = 0.f, accp = 0.f;
    #pragma unroll
    for (int it = 0; it < 4; ++it) {
        int gcol = t + it * 256;
        float4 e = e4[it];
        float gs = (e.x + e.y) + (e.z + e.w);
        float base = rs - gs - EXP10;
        if (gcol != gr) {
            acc += __logf(base + e.x + e.y) + __logf(base + e.x + e.z)
                 + __logf(base + e.x + e.w) + __logf(base + e.y + e.z)
                 + __logf(base + e.y + e.w) + __logf(base + e.z + e.w);
        } else {
            float ee[4] = {e.x, e.y, e.z, e.w};
            #pragma unroll
            for (int a = 0; a < 4; ++a)
                #pragma unroll
                for (int b = a + 1; b < 4; ++b)
                    if (a == kk || b == kk) acc += __logf(base + ee[a] + ee[b]);
            #pragma unroll
            for (int m = 0; m < 4; ++m)
                if (m != kk) accp += __logf(ee[m]);
        }
    }

    #pragma unroll
    for (int off = 16; off > 0; off >>= 1) {
        acc  += __shfl_down_sync(0xffffffffu, acc,  off);
        accp += __shfl_down_sync(0xffffffffu, accp, off);
    }
    __shared__ float wa[8], wp[8];
    if ((t & 31) == 0) { wa[t >> 5] = acc; wp[t >> 5] = accp; }
    __syncthreads();
    if (t == 0) {
        float a = 0.f, p = 0.f;
        #pragma unroll
        for (int ww = 0; ww < 8; ++ww) { a += wa[ww]; p += wp[ww]; }
        g_rowL[r] = a;
        g_rowP[r] = p;
    }
}

// ---------------- kernel 4: final deterministic combine --------------------
__global__ void k_finalize(float* __restrict__ out) {
    __shared__ double sa[256], sp[256];
    int t = threadIdx.x;
    double a = 0.0, p = 0.0;
    for (int r = t; r < NSEG; r += 256) { a += (double)g_rowL[r]; p += (double)g_rowP[r]; }
    sa[t] = a; sp[t] = p;
    __syncthreads();
    for (int s = 128; s > 0; s >>= 1) {
        if (t < s) { sa[t] += sa[t + s]; sp[t] += sp[t + s]; }
        __syncthreads();
    }
    if (t == 0) out[0] = (float)(sa[0] * (2.0 / 4094.0) - sp[0]);
}

// ---------------- launch ---------------------------------------------------
extern "C" void kernel_launch(void* const* d_in, const int* in_sizes, int n_in,
                              void* d_out, int out_size) {
    const float* feats = (const float*)d_in[0];
    float* out = (float*)d_out;

    cudaFuncSetAttribute(k_gemm_exp, cudaFuncAttributeMaxDynamicSharedMemorySize, SMEM2);

    k_norm<<<512, 256>>>(feats);
    k_gemm_exp<<<dim3(32, 32), 256, SMEM2>>>();
    k_rssum<<<16, 256>>>();
    k_loss<<<NSEG, 256>>>();
    k_finalize<<<1, 256>>>(out);
}

// round 5
// speedup vs baseline: 3.2833x; 1.2574x over previous
#include <cuda_runtime.h>
#include <cuda_fp16.h>
#include <cstdint>

#define NSEG 4096
#define DIM  128
#define C_EXP2  14.426950408889634f   // (1/T)/ln2 = 10/ln2
#define EXP10   22026.465794806718f   // exp(1/T) = exp(10)

// ---------------- device scratch (static: no allocations allowed) ----------
__device__ __half g_Fh[NSEG * DIM];          // normalized feats [m][k], fp16, 1 MB
__device__ __half g_Eh[16777216];            // exp(S/T) fp16, row-major [4096][4096], 32 MB
__device__ float g_RSpart[32 * NSEG];        // per-colblock row-sum partials
__device__ float g_RS[NSEG];                 // full row sums of E
__device__ float g_rowL[NSEG];               // per-row log-sum partial
__device__ float g_rowP[NSEG];               // per-row pair (S/T) partial

__device__ __forceinline__ uint32_t smem_u32(const void* p) {
    uint32_t a;
    asm("{ .reg .u64 t; cvta.to.shared.u64 t, %1; cvt.u32.u64 %0, t; }" : "=r"(a) : "l"(p));
    return a;
}
#define LDSM_X4(r0, r1, r2, r3, addr) \
    asm volatile("ldmatrix.sync.aligned.m8n8.x4.shared.b16 {%0,%1,%2,%3}, [%4];" \
        : "=r"(r0), "=r"(r1), "=r"(r2), "=r"(r3) : "r"(addr))
#define MOVM_T(d, s) \
    asm("movmatrix.sync.aligned.m8n8.trans.b16 %0, %1;" : "=r"(d) : "r"(s))

// ---------------- kernel 1: normalize rows -> g_Fh (fp16), warp/row -------
__global__ void k_norm(const float* __restrict__ feats) {
    const int w = threadIdx.x >> 5, lane = threadIdx.x & 31;
    const int row = blockIdx.x * 8 + w;
    float4 v = *reinterpret_cast<const float4*>(&feats[row * DIM + lane * 4]);
    float sum = fmaf(v.x, v.x, fmaf(v.y, v.y, fmaf(v.z, v.z, v.w * v.w)));
    #pragma unroll
    for (int off = 16; off > 0; off >>= 1) sum += __shfl_xor_sync(0xffffffffu, sum, off);
    float inv = rsqrtf(sum);
    inv = inv * (1.5f - 0.5f * sum * inv * inv);   // NR refine
    __half2 h0 = __floats2half2_rn(v.x * inv, v.y * inv);
    __half2 h1 = __floats2half2_rn(v.z * inv, v.w * inv);
    *reinterpret_cast<__half2*>(&g_Fh[row * DIM + lane * 4])     = h0;
    *reinterpret_cast<__half2*>(&g_Fh[row * DIM + lane * 4 + 2]) = h1;
}

// ---------------- kernel 2: fp16 HMMA GEMM (upper-tri) -> exp -> E(fp16) ---
// Linear grid of 528 upper-triangular 128x128 tiles. 8 warps as 4(m) x 2(n),
// warp tile 32x64, mma.m16n8k16, ldmatrix.x4 operand loads, movmatrix for the
// register-level transposed (mirror) store.
#define LDH 136                       // padded row stride in halfs (272 B)
#define SMEM2 (2 * 128 * LDH * 2)     // 69632 B

__global__ void __launch_bounds__(256, 2) k_gemm_exp() {
    // triangular decode: tile p -> (bi, bj), bi <= bj
    int p = blockIdx.x, bi = 0, cnt = 32;
    while (p >= cnt) { p -= cnt; ++bi; --cnt; }
    const int bj = bi + p;
    const bool diag = (bi == bj);

    extern __shared__ char smem[];
    __half* As = reinterpret_cast<__half*>(smem);
    __half* Bs = As + 128 * LDH;
    const int tid = threadIdx.x;
    const int w = tid >> 5, lane = tid & 31;
    const int g = lane >> 2, t = lane & 3;
    const int warp_m = w & 3, warp_n = w >> 2;
    const int rowbase = bi * 128, colbase = bj * 128;

    // coalesced tile fill (uint4 = 8 halfs)
    for (int idx = tid; idx < 128 * 16; idx += 256) {
        int m = idx >> 4, c8 = (idx & 15) * 8;
        uint4 a = *reinterpret_cast<const uint4*>(&g_Fh[(rowbase + m) * DIM + c8]);
        uint4 b = *reinterpret_cast<const uint4*>(&g_Fh[(colbase + m) * DIM + c8]);
        *reinterpret_cast<uint4*>(&As[m * LDH + c8]) = a;
        *reinterpret_cast<uint4*>(&Bs[m * LDH + c8]) = b;
    }
    __syncthreads();

    // ldmatrix per-lane addresses. matrix idx mm = lane>>3.
    // A x4 order: [r+0 k0][r+8 k0][r+0 k8][r+8 k8] -> {a0,a1,a2,a3}
    // B x4 order: [n+0 k0][n+0 k8][n+8 k0][n+8 k8] -> {b_nt0_0,b_nt0_1,b_nt1_0,b_nt1_1}
    const int mm = lane >> 3;
    const uint32_t As_b = smem_u32(As), Bs_b = smem_u32(Bs);
    uint32_t aAddr[2], bAddr[4];
    #pragma unroll
    for (int mt = 0; mt < 2; ++mt)
        aAddr[mt] = As_b + (uint32_t)(((warp_m * 32 + mt * 16 + (mm & 1) * 8 + (lane & 7)) * LDH
                                       + (mm >> 1) * 8) * 2);
    #pragma unroll
    for (int np = 0; np < 4; ++np)
        bAddr[np] = Bs_b + (uint32_t)(((warp_n * 64 + np * 16 + (mm >> 1) * 8 + (lane & 7)) * LDH
                                       + (mm & 1) * 8) * 2);

    float c[2][8][4];
    #pragma unroll
    for (int mt = 0; mt < 2; ++mt)
        #pragma unroll
        for (int nt = 0; nt < 8; ++nt)
            #pragma unroll
            for (int q = 0; q < 4; ++q) c[mt][nt][q] = 0.f;

    #pragma unroll
    for (int ks = 0; ks < 8; ++ks) {
        const uint32_t koff = ks * 32;   // 16 halfs
        uint32_t a[2][4], b[4][4];
        #pragma unroll
        for (int mt = 0; mt < 2; ++mt)
            LDSM_X4(a[mt][0], a[mt][1], a[mt][2], a[mt][3], aAddr[mt] + koff);
        #pragma unroll
        for (int np = 0; np < 4; ++np)
            LDSM_X4(b[np][0], b[np][1], b[np][2], b[np][3], bAddr[np] + koff);
        #pragma unroll
        for (int mt = 0; mt < 2; ++mt)
            #pragma unroll
            for (int nt = 0; nt < 8; ++nt)
                asm volatile(
                    "mma.sync.aligned.m16n8k16.row.col.f32.f16.f16.f32 "
                    "{%0,%1,%2,%3}, {%4,%5,%6,%7}, {%8,%9}, {%0,%1,%2,%3};"
                    : "+f"(c[mt][nt][0]), "+f"(c[mt][nt][1]),
                      "+f"(c[mt][nt][2]), "+f"(c[mt][nt][3])
                    : "r"(a[mt][0]), "r"(a[mt][1]), "r"(a[mt][2]), "r"(a[mt][3]),
                      "r"(b[nt >> 1][(nt & 1) * 2]), "r"(b[nt >> 1][(nt & 1) * 2 + 1]));
    }

    __syncthreads();   // mainloop smem dead; reuse front of it for reductions
    float* rs = reinterpret_cast<float*>(smem);          // [2][128]
    float* cs = reinterpret_cast<float*>(smem + 1024);   // [128][4]

    // epilogue: exp -> fp16, direct store, movmatrix-transposed mirror store,
    // row sums (quad reduce) and column sums (g reduce).
    float rs0[2] = {0.f, 0.f}, rs1[2] = {0.f, 0.f};
    #pragma unroll
    for (int nt = 0; nt < 8; ++nt) {
        float cs0 = 0.f, cs1 = 0.f;
        #pragma unroll
        for (int mt = 0; mt < 2; ++mt) {
            const int r0 = warp_m * 32 + mt * 16;
            const int c0 = warp_n * 64 + nt * 8;
            const int r_lo = rowbase + r0 + g;
            const int col  = colbase + c0 + 2 * t;
            float e0 = exp2f(c[mt][nt][0] * C_EXP2);
            float e1 = exp2f(c[mt][nt][1] * C_EXP2);
            float e2 = exp2f(c[mt][nt][2] * C_EXP2);
            float e3 = exp2f(c[mt][nt][3] * C_EXP2);
            rs0[mt] += e0 + e1;
            rs1[mt] += e2 + e3;
            cs0 += e0 + e2;
            cs1 += e1 + e3;
            uint32_t hlo, hhi;
            asm("cvt.rn.f16x2.f32 %0, %1, %2;" : "=r"(hlo) : "f"(e1), "f"(e0));
            asm("cvt.rn.f16x2.f32 %0, %1, %2;" : "=r"(hhi) : "f"(e3), "f"(e2));
            *reinterpret_cast<uint32_t*>(&g_Eh[(size_t)r_lo * NSEG + col])       = hlo;
            *reinterpret_cast<uint32_t*>(&g_Eh[(size_t)(r_lo + 8) * NSEG + col]) = hhi;
            if (!diag) {
                uint32_t tlo, thi;
                MOVM_T(tlo, hlo);
                MOVM_T(thi, hhi);
                *reinterpret_cast<uint32_t*>(
                    &g_Eh[(size_t)(colbase + c0 + g) * NSEG + rowbase + r0 + 2 * t])     = tlo;
                *reinterpret_cast<uint32_t*>(
                    &g_Eh[(size_t)(colbase + c0 + g) * NSEG + rowbase + r0 + 8 + 2 * t]) = thi;
            }
        }
        if (!diag) {
            #pragma unroll
            for (int off = 4; off <= 16; off <<= 1) {
                cs0 += __shfl_xor_sync(0xffffffffu, cs0, off);
                cs1 += __shfl_xor_sync(0xffffffffu, cs1, off);
            }
            if (lane < 4) {   // lane == t, g == 0
                cs[(warp_n * 64 + nt * 8 + 2 * t) * 4 + warp_m]     = cs0;
                cs[(warp_n * 64 + nt * 8 + 2 * t + 1) * 4 + warp_m] = cs1;
            }
        }
    }
    // quad-reduce row sums (over t)
    #pragma unroll
    for (int mt = 0; mt < 2; ++mt) {
        #pragma unroll
        for (int off = 1; off <= 2; off <<= 1) {
            rs0[mt] += __shfl_xor_sync(0xffffffffu, rs0[mt], off);
            rs1[mt] += __shfl_xor_sync(0xffffffffu, rs1[mt], off);
        }
        if (t == 0) {
            rs[warp_n * 128 + warp_m * 32 + mt * 16 + g]     = rs0[mt];
            rs[warp_n * 128 + warp_m * 32 + mt * 16 + g + 8] = rs1[mt];
        }
    }
    __syncthreads();
    if (tid < 128) {
        g_RSpart[(size_t)bj * NSEG + rowbase + tid] = rs[tid] + rs[128 + tid];
        if (!diag)
            g_RSpart[(size_t)bi * NSEG + colbase + tid] =
                (cs[tid * 4] + cs[tid * 4 + 1]) + (cs[tid * 4 + 2] + cs[tid * 4 + 3]);
    }
}

// ---------------- kernel 2.5: deterministic row-sum combine ----------------
__global__ void k_rssum() {
    int r = blockIdx.x * blockDim.x + threadIdx.x;
    float s = 0.f;
    #pragma unroll
    for (int j = 0; j < 32; ++j) s += g_RSpart[j * NSEG + r];
    g_RS[r] = s;
}

// ---------------- kernel 3: per-row loss reduction (fp16 E) ----------------
__device__ __forceinline__ void loss_group(uint32_t w0, uint32_t w1, int gcol,
                                           int gr, int kk, float base_rs,
                                           float& acc, float& accp) {
    float2 f01 = __half22float2(reinterpret_cast<const __half2&>(w0));
    float2 f23 = __half22float2(reinterpret_cast<const __half2&>(w1));
    float ex = f01.x, ey = f01.y, ez = f23.x, ew = f23.y;
    float gs = (ex + ey) + (ez + ew);
    float base = base_rs - gs - EXP10;
    if (gcol != gr) {
        acc += __logf(base + ex + ey) + __logf(base + ex + ez)
             + __logf(base + ex + ew) + __logf(base + ey + ez)
             + __logf(base + ey + ew) + __logf(base + ez + ew);
    } else {
        float ee[4] = {ex, ey, ez, ew};
        #pragma unroll
        for (int a = 0; a < 4; ++a)
            #pragma unroll
            for (int b = a + 1; b < 4; ++b)
                if (a == kk || b == kk) acc += __logf(base + ee[a] + ee[b]);
        #pragma unroll
        for (int m = 0; m < 4; ++m)
            if (m != kk) accp += __logf(ee[m]);
    }
}

__global__ void k_loss() {
    const int r = blockIdx.x;
    const int t = threadIdx.x;
    const float rs = g_RS[r];
    const int gr = r >> 2;
    const int kk = r & 3;
    const uint4* Er = reinterpret_cast<const uint4*>(&g_Eh[(size_t)r * NSEG]);

    uint4 u0 = Er[t], u1 = Er[t + 256];   // front-batched (MLP=2, 16B each)

    float acc = 0.f, accp = 0.f;
    loss_group(u0.x, u0.y, 2 * t,           gr, kk, rs, acc, accp);
    loss_group(u0.z, u0.w, 2 * t + 1,       gr, kk, rs, acc, accp);
    loss_group(u1.x, u1.y, 2 * (t + 256),   gr, kk, rs, acc, accp);
    loss_group(u1.z, u1.w, 2 * (t + 256) + 1, gr, kk, rs, acc, accp);

    #pragma unroll
    for (int off = 16; off > 0; off >>= 1) {
        acc  += __shfl_down_sync(0xffffffffu, acc,  off);
        accp += __shfl_down_sync(0xffffffffu, accp, off);
    }
    __shared__ float wa[8], wp[8];
    if ((t & 31) == 0) { wa[t >> 5] = acc; wp[t >> 5] = accp; }
    __syncthreads();
    if (t == 0) {
        float a = 0.f, p = 0.f;
        #pragma unroll
        for (int ww = 0; ww < 8; ++ww) { a += wa[ww]; p += wp[ww]; }
        g_rowL[r] = a;
        g_rowP[r] = p;
    }
}

// ---------------- kernel 4: final deterministic combine --------------------
__global__ void k_finalize(float* __restrict__ out) {
    __shared__ double sa[256], sp[256];
    int t = threadIdx.x;
    double a = 0.0, p = 0.0;
    for (int r = t; r < NSEG; r += 256) { a += (double)g_rowL[r]; p += (double)g_rowP[r]; }
    sa[t] = a; sp[t] = p;
    __syncthreads();
    for (int s = 128; s > 0; s >>= 1) {
        if (t < s) { sa[t] += sa[t + s]; sp[t] += sp[t + s]; }
        __syncthreads();
    }
    if (t == 0) out[0] = (float)(sa[0] * (2.0 / 4094.0) - sp[0]);
}

// ---------------- launch ---------------------------------------------------
extern "C" void kernel_launch(void* const* d_in, const int* in_sizes, int n_in,
                              void* d_out, int out_size) {
    const float* feats = (const float*)d_in[0];
    float* out = (float*)d_out;

    cudaFuncSetAttribute(k_gemm_exp, cudaFuncAttributeMaxDynamicSharedMemorySize, SMEM2);

    k_norm<<<512, 256>>>(feats);
    k_gemm_exp<<<528, 256, SMEM2>>>();
    k_rssum<<<16, 256>>>();
    k_loss<<<NSEG, 256>>>();
    k_finalize<<<1, 256>>>(out);
}